// round 4
// baseline (speedup 1.0000x reference)
#include <cuda_runtime.h>
#include <cstdint>

// Problem constants
#define Bn 4
#define Cn 32
#define Ln 256
#define Mn 256
#define Fn 8
#define Nn 64
#define FC (Fn * Cn)          // 256
#define LM (Ln * Mn)          // 65536
#define IMAG_OFF ((size_t)Bn * Fn * LM)  // 2,097,152

union U64 {
    unsigned long long u;
    float2 f;
};

__device__ __forceinline__ unsigned long long ffma2(unsigned long long a,
                                                    unsigned long long b,
                                                    unsigned long long c) {
    unsigned long long d;
    asm("fma.rn.f32x2 %0, %1, %2, %3;" : "=l"(d) : "l"(a), "l"(b), "l"(c));
    return d;
}

// ---------------------------------------------------------------------------
// Grid: B*L = 1024 blocks, 128 threads.
// Threads 0-63  handle f = 0..3 for m = (tid&63)*4 .. +3
// Threads 64-127 handle f = 4..7 for the same m (x lines shared via L1).
// Each thread: 4 m via LDG.128, 16 u64 accumulators, depth-2 c prefetch.
// ---------------------------------------------------------------------------
__global__ __launch_bounds__(128, 8) void sphere_v4_kernel(
    const float* __restrict__ xr,
    const float* __restrict__ xi,
    const float* __restrict__ wr,
    const float* __restrict__ wi,
    float* __restrict__ out) {
    __shared__ ulonglong2 s2[FC];   // 4 KB: { {wr,wr}, {wi,wi} } per (f,c)

    int bid = blockIdx.x;
    int b = bid >> 8;
    int l = bid & (Ln - 1);
    int tid = threadIdx.x;

    // --- interpolate this l's weights into shared ---
    {
        float t = (float)l * (63.0f / 255.0f);
        int lo = (int)t;
        if (lo > Nn - 2) lo = Nn - 2;
        float fr = t - (float)lo;
        float om = 1.0f - fr;
#pragma unroll
        for (int j = 0; j < 2; ++j) {
            int k = tid + j * 128;            // k = f*C + c
            const float* pwr = wr + k * Nn + lo;
            const float* pwi = wi + k * Nn + lo;
            float vr = pwr[0] * om + pwr[1] * fr;
            float vi = pwi[0] * om + pwi[1] * fr;
            U64 ur, ui;
            ur.f = make_float2(vr, vr);
            ui.f = make_float2(vi, vi);
            s2[k] = make_ulonglong2(ur.u, ui.u);
        }
    }
    __syncthreads();

    int fb = (tid >> 6) * 4;            // f base: 0 or 4
    int m0 = (tid & 63) * 4;
    const ulonglong2* pr = reinterpret_cast<const ulonglong2*>(
        xr + (size_t)b * Cn * LM + (size_t)l * Mn + m0);
    const ulonglong2* pi = reinterpret_cast<const ulonglong2*>(
        xi + (size_t)b * Cn * LM + (size_t)l * Mn + m0);
    const size_t step = LM / 4;          // ulonglong2 elements per c

    unsigned long long ar[4][2], ai[4][2];
#pragma unroll
    for (int f = 0; f < 4; ++f) {
        ar[f][0] = 0ull; ar[f][1] = 0ull;
        ai[f][0] = 0ull; ai[f][1] = 0ull;
    }

    // depth-2 register double buffer
    ulonglong2 r0 = pr[0], i0 = pi[0];
    ulonglong2 r1 = pr[step], i1 = pi[step];

    const unsigned long long SM = 0x8000000080000000ULL;

#pragma unroll
    for (int c = 0; c < Cn; c += 2) {
        // ---- even c ----
        ulonglong2 rc = r0, ic = i0;
        if (c + 2 < Cn) { r0 = pr[(size_t)(c + 2) * step]; i0 = pi[(size_t)(c + 2) * step]; }
        {
            unsigned long long nx0 = ic.x ^ SM, nx1 = ic.y ^ SM;
#pragma unroll
            for (int f = 0; f < 4; ++f) {
                ulonglong2 w = s2[(fb + f) * Cn + c];
                ar[f][0] = ffma2(w.x, rc.x, ar[f][0]);
                ar[f][0] = ffma2(w.y, nx0,  ar[f][0]);
                ar[f][1] = ffma2(w.x, rc.y, ar[f][1]);
                ar[f][1] = ffma2(w.y, nx1,  ar[f][1]);
                ai[f][0] = ffma2(w.x, ic.x, ai[f][0]);
                ai[f][0] = ffma2(w.y, rc.x, ai[f][0]);
                ai[f][1] = ffma2(w.x, ic.y, ai[f][1]);
                ai[f][1] = ffma2(w.y, rc.y, ai[f][1]);
            }
        }
        // ---- odd c ----
        ulonglong2 rd = r1, id = i1;
        if (c + 3 < Cn) { r1 = pr[(size_t)(c + 3) * step]; i1 = pi[(size_t)(c + 3) * step]; }
        {
            unsigned long long nx0 = id.x ^ SM, nx1 = id.y ^ SM;
#pragma unroll
            for (int f = 0; f < 4; ++f) {
                ulonglong2 w = s2[(fb + f) * Cn + c + 1];
                ar[f][0] = ffma2(w.x, rd.x, ar[f][0]);
                ar[f][0] = ffma2(w.y, nx0,  ar[f][0]);
                ar[f][1] = ffma2(w.x, rd.y, ar[f][1]);
                ar[f][1] = ffma2(w.y, nx1,  ar[f][1]);
                ai[f][0] = ffma2(w.x, id.x, ai[f][0]);
                ai[f][0] = ffma2(w.y, rd.x, ai[f][0]);
                ai[f][1] = ffma2(w.x, id.y, ai[f][1]);
                ai[f][1] = ffma2(w.y, rd.y, ai[f][1]);
            }
        }
    }

    float sc = sqrtf(1.0f + (float)l) * (1.0f / 32.0f);
    float* obase = out + (size_t)(b * Fn + fb) * LM + (size_t)l * Mn + m0;

#pragma unroll
    for (int f = 0; f < 4; ++f) {
        U64 u0, u1;
        u0.u = ar[f][0]; u1.u = ar[f][1];
        float4 vr4;
        vr4.x = fmaxf(u0.f.x * sc, 0.0f);
        vr4.y = fmaxf(u0.f.y * sc, 0.0f);
        vr4.z = fmaxf(u1.f.x * sc, 0.0f);
        vr4.w = fmaxf(u1.f.y * sc, 0.0f);
        *reinterpret_cast<float4*>(obase + (size_t)f * LM) = vr4;

        u0.u = ai[f][0]; u1.u = ai[f][1];
        float4 vi4;
        vi4.x = u0.f.x * sc;
        vi4.y = u0.f.y * sc;
        vi4.z = u1.f.x * sc;
        vi4.w = u1.f.y * sc;
        *reinterpret_cast<float4*>(obase + IMAG_OFF + (size_t)f * LM) = vi4;
    }
}

extern "C" void kernel_launch(void* const* d_in, const int* in_sizes, int n_in,
                              void* d_out, int out_size) {
    const float* x_real = (const float*)d_in[0];
    const float* x_imag = (const float*)d_in[1];
    const float* w_real = (const float*)d_in[2];
    const float* w_imag = (const float*)d_in[3];
    float* out = (float*)d_out;

    sphere_v4_kernel<<<Bn * Ln, 128>>>(x_real, x_imag, w_real, w_imag, out);
}

// round 5
// speedup vs baseline: 1.0013x; 1.0013x over previous
#include <cuda_runtime.h>
#include <cstdint>

// Problem constants
#define Bn 4
#define Cn 32
#define Ln 256
#define Mn 256
#define Fn 8
#define Nn 64
#define FC (Fn * Cn)          // 256
#define LM (Ln * Mn)          // 65536
#define IMAG_OFF ((size_t)Bn * Fn * LM)  // 2,097,152

#define STAGES 4
#define CPC 4                 // channels per chunk
#define NCHUNK (Cn / CPC)     // 8
#define CHUNK_BYTES (CPC * Mn * 4 * 2)   // 8192 (xr + xi)
#define STAGE_BYTES (CPC * Mn * 4 * 2)   // 8192

union U64 {
    unsigned long long u;
    float2 f;
};

__device__ __forceinline__ unsigned long long ffma2(unsigned long long a,
                                                    unsigned long long b,
                                                    unsigned long long c) {
    unsigned long long d;
    asm("fma.rn.f32x2 %0, %1, %2, %3;" : "=l"(d) : "l"(a), "l"(b), "l"(c));
    return d;
}

__device__ __forceinline__ uint32_t smem_u32(const void* p) {
    uint32_t a;
    asm("{ .reg .u64 t; cvta.to.shared.u64 t, %1; cvt.u32.u64 %0, t; }"
        : "=r"(a) : "l"(p));
    return a;
}

__device__ __forceinline__ void bulk_cp(uint32_t sdst, const void* gsrc,
                                        uint32_t bytes, uint32_t bar) {
    asm volatile(
        "cp.async.bulk.shared::cta.global.mbarrier::complete_tx::bytes "
        "[%0], [%1], %2, [%3];"
        :: "r"(sdst), "l"(gsrc), "r"(bytes), "r"(bar) : "memory");
}

__device__ __forceinline__ void mbar_init(uint32_t bar, uint32_t count) {
    asm volatile("mbarrier.init.shared.b64 [%0], %1;" :: "r"(bar), "r"(count)
                 : "memory");
}

__device__ __forceinline__ void mbar_expect_tx(uint32_t bar, uint32_t bytes) {
    asm volatile("mbarrier.arrive.expect_tx.shared.b64 _, [%0], %1;"
                 :: "r"(bar), "r"(bytes) : "memory");
}

__device__ __forceinline__ void mbar_wait(uint32_t bar, uint32_t parity) {
    asm volatile(
        "{\n\t"
        ".reg .pred P;\n\t"
        "WAIT_%=:\n\t"
        "mbarrier.try_wait.parity.acquire.cta.shared::cta.b64 P, [%0], %1;\n\t"
        "@P bra DONE_%=;\n\t"
        "bra WAIT_%=;\n\t"
        "DONE_%=:\n\t"
        "}"
        :: "r"(bar), "r"(parity) : "memory");
}

// ---------------------------------------------------------------------------
// Grid: B*L = 1024 blocks, 256 threads. Block handles one (b, l).
// x rows streamed in via cp.async.bulk ring (4 stages x 4 channels).
// Thread t: m-pair = t&127, f-half = t>>7 (f 0-3 or 4-7). 8 u64 accumulators.
// ---------------------------------------------------------------------------
__global__ __launch_bounds__(256, 6) void sphere_bulk_kernel(
    const float* __restrict__ xr,
    const float* __restrict__ xi,
    const float* __restrict__ wr,
    const float* __restrict__ wi,
    float* __restrict__ out) {
    __shared__ __align__(16) float sx[STAGES][2][CPC][Mn];   // 32 KB
    __shared__ ulonglong2 s2[FC];                            // 4 KB weights
    __shared__ __align__(8) unsigned long long mbar[STAGES];

    int bid = blockIdx.x;
    int b = bid >> 8;
    int l = bid & (Ln - 1);
    int tid = threadIdx.x;

    // --- interpolate this l's weights into shared (one k per thread) ---
    {
        float t = (float)l * (63.0f / 255.0f);
        int lo = (int)t;
        if (lo > Nn - 2) lo = Nn - 2;
        float fr = t - (float)lo;
        float om = 1.0f - fr;
        int k = tid;
        const float* pwr = wr + k * Nn + lo;
        const float* pwi = wi + k * Nn + lo;
        float vr = pwr[0] * om + pwr[1] * fr;
        float vi = pwi[0] * om + pwi[1] * fr;
        U64 ur, ui;
        ur.f = make_float2(vr, vr);
        ui.f = make_float2(vi, vi);
        s2[k] = make_ulonglong2(ur.u, ui.u);
    }

    uint32_t sbase = smem_u32(&sx[0][0][0][0]);
    uint32_t barb = smem_u32(&mbar[0]);

    if (tid == 0) {
#pragma unroll
        for (int s = 0; s < STAGES; ++s) mbar_init(barb + s * 8, 1);
        asm volatile("fence.proxy.async.shared::cta;" ::: "memory");
    }
    __syncthreads();

    const char* gxr = reinterpret_cast<const char*>(
        xr + (size_t)b * Cn * LM + (size_t)l * Mn);
    const char* gxi = reinterpret_cast<const char*>(
        xi + (size_t)b * Cn * LM + (size_t)l * Mn);

    // prologue: issue chunks 0..3 (fills all stages)
    if (tid == 0) {
#pragma unroll
        for (int k = 0; k < STAGES; ++k) {
            uint32_t bar = barb + (k & (STAGES - 1)) * 8;
            uint32_t sdst = sbase + (k & (STAGES - 1)) * STAGE_BYTES;
            mbar_expect_tx(bar, CHUNK_BYTES);
#pragma unroll
            for (int j = 0; j < CPC; ++j) {
                size_t c = (size_t)(k * CPC + j);
                bulk_cp(sdst + j * 1024, gxr + c * (LM * 4), 1024, bar);
                bulk_cp(sdst + CPC * 1024 + j * 1024, gxi + c * (LM * 4), 1024, bar);
            }
        }
    }

    int mp = tid & 127;
    int fb = (tid >> 7) * 4;   // f base 0 or 4

    unsigned long long ar[4], ai[4];
#pragma unroll
    for (int f = 0; f < 4; ++f) { ar[f] = 0ull; ai[f] = 0ull; }

    const unsigned long long SMSK = 0x8000000080000000ULL;

#pragma unroll
    for (int cc = 0; cc < NCHUNK; ++cc) {
        int s = cc & (STAGES - 1);
        mbar_wait(barb + s * 8, cc >> 2);

#pragma unroll
        for (int j = 0; j < CPC; ++j) {
            int c = cc * CPC + j;
            unsigned long long xrc =
                *reinterpret_cast<const unsigned long long*>(&sx[s][0][j][mp * 2]);
            unsigned long long xic =
                *reinterpret_cast<const unsigned long long*>(&sx[s][1][j][mp * 2]);
            unsigned long long nxi = xic ^ SMSK;
#pragma unroll
            for (int f = 0; f < 4; ++f) {
                ulonglong2 w = s2[(fb + f) * Cn + c];   // broadcast LDS.128
                ar[f] = ffma2(w.x, xrc, ar[f]);
                ar[f] = ffma2(w.y, nxi, ar[f]);
                ai[f] = ffma2(w.x, xic, ai[f]);
                ai[f] = ffma2(w.y, xrc, ai[f]);
            }
        }
        __syncthreads();   // stage s free for reuse

        int kn = cc + STAGES;
        if (tid == 0 && kn < NCHUNK) {
            uint32_t bar = barb + s * 8;
            uint32_t sdst = sbase + s * STAGE_BYTES;
            mbar_expect_tx(bar, CHUNK_BYTES);
#pragma unroll
            for (int j = 0; j < CPC; ++j) {
                size_t c = (size_t)(kn * CPC + j);
                bulk_cp(sdst + j * 1024, gxr + c * (LM * 4), 1024, bar);
                bulk_cp(sdst + CPC * 1024 + j * 1024, gxi + c * (LM * 4), 1024, bar);
            }
        }
    }

    float sc = sqrtf(1.0f + (float)l) * (1.0f / 32.0f);
    float* obase = out + (size_t)(b * Fn + fb) * LM + (size_t)l * Mn + mp * 2;

#pragma unroll
    for (int f = 0; f < 4; ++f) {
        U64 u;
        u.u = ar[f];
        float2 vr2;
        vr2.x = fmaxf(u.f.x * sc, 0.0f);
        vr2.y = fmaxf(u.f.y * sc, 0.0f);
        *reinterpret_cast<float2*>(obase + (size_t)f * LM) = vr2;

        u.u = ai[f];
        float2 vi2;
        vi2.x = u.f.x * sc;
        vi2.y = u.f.y * sc;
        *reinterpret_cast<float2*>(obase + IMAG_OFF + (size_t)f * LM) = vi2;
    }
}

extern "C" void kernel_launch(void* const* d_in, const int* in_sizes, int n_in,
                              void* d_out, int out_size) {
    const float* x_real = (const float*)d_in[0];
    const float* x_imag = (const float*)d_in[1];
    const float* w_real = (const float*)d_in[2];
    const float* w_imag = (const float*)d_in[3];
    float* out = (float*)d_out;

    sphere_bulk_kernel<<<Bn * Ln, 256>>>(x_real, x_imag, w_real, w_imag, out);
}